// round 13
// baseline (speedup 1.0000x reference)
#include <cuda_runtime.h>
#include <cstdint>
#include <math.h>

#define B_SZ 4096
#define T_SZ 2048
#define WARPS_PER_BLOCK 4
#define NBLOCKS (B_SZ / WARPS_PER_BLOCK)   // 1024
#define STAGES 4                            // smem ring depth
#define NSTG 8                              // 8 stages of 2KB per 16KB row
#define WIN_PER_STG 4                       // 4 windows (64 steps) per stage
#define STG_BYTES 2048
#define DT 0.01f

// Per-block partials: (sum_wq2, sum_wp2, penalty_sum, unused)
__device__ float4 g_blk[NBLOCKS];
__device__ unsigned g_cnt = 0;

struct M2f { float a, b, c, d; };   // [[a,b],[c,d]]

__device__ __forceinline__ M2f m2mul(const M2f& X, const M2f& Y) {
    M2f r;
    r.a = fmaf(X.a, Y.a, X.b * Y.c);
    r.b = fmaf(X.a, Y.b, X.b * Y.d);
    r.c = fmaf(X.c, Y.a, X.d * Y.c);
    r.d = fmaf(X.c, Y.b, X.d * Y.d);
    return r;
}

__device__ __forceinline__ void mbar_init(unsigned mbar, unsigned count) {
    asm volatile("mbarrier.init.shared.b64 [%0], %1;" :: "r"(mbar), "r"(count) : "memory");
}
__device__ __forceinline__ void mbar_expect_tx(unsigned mbar, unsigned bytes) {
    asm volatile("mbarrier.arrive.expect_tx.shared.b64 _, [%0], %1;"
                 :: "r"(mbar), "r"(bytes) : "memory");
}
__device__ __forceinline__ void bulk_g2s(unsigned dst, const void* src,
                                         unsigned bytes, unsigned mbar) {
    asm volatile("cp.async.bulk.shared::cluster.global.mbarrier::complete_tx::bytes "
                 "[%0], [%1], %2, [%3];"
                 :: "r"(dst), "l"(src), "r"(bytes), "r"(mbar) : "memory");
}
__device__ __forceinline__ void mbar_wait(unsigned mbar, unsigned parity) {
    asm volatile(
        "{\n\t"
        ".reg .pred P1;\n\t"
        "WAIT_%=:\n\t"
        "mbarrier.try_wait.parity.acquire.cta.shared::cta.b64 P1, [%0], %1, 0x989680;\n\t"
        "@P1 bra.uni DONE_%=;\n\t"
        "bra.uni WAIT_%=;\n\t"
        "DONE_%=:\n\t"
        "}"
        :: "r"(mbar), "r"(parity) : "memory");
}

__global__ void __launch_bounds__(WARPS_PER_BLOCK * 32)
rollout_kernel(const float* __restrict__ x, const float* __restrict__ y_pred,
               float* __restrict__ out)
{
    // smem ring: [warp][stage][window][lane] = 32 KB
    __shared__ float4 stg[WARPS_PER_BLOCK][STAGES][WIN_PER_STG][32];
    __shared__ unsigned long long mbar_s[WARPS_PER_BLOCK][STAGES];
    __shared__ float s_q[WARPS_PER_BLOCK], s_p[WARPS_PER_BLOCK], s_n[WARPS_PER_BLOCK];
    __shared__ double fsq[128], fsp[128], fsn[128];
    __shared__ bool isLast;

    const int wid  = threadIdx.x >> 5;
    const int lane = threadIdx.x & 31;
    const int bidx = blockIdx.x * WARPS_PER_BLOCK + wid;   // batch index

    const char* xrow = (const char*)x + (size_t)bidx * (T_SZ * 2 * 4);  // 16KB row
    const unsigned mb0 =
        (unsigned)__cvta_generic_to_shared(&mbar_s[wid][0]);
    const unsigned sg0 =
        (unsigned)__cvta_generic_to_shared(&stg[wid][0][0][0]);

    // ---- init mbarriers (count=1: the expect_tx arrive) ----
    if (lane == 0) {
        #pragma unroll
        for (int s = 0; s < STAGES; ++s) mbar_init(mb0 + 8u * s, 1u);
        asm volatile("fence.proxy.async.shared::cta;" ::: "memory");
    }
    __syncthreads();

    // ---- kick off 3 stages of bulk copies immediately ----
    if (lane == 0) {
        #pragma unroll
        for (int s = 0; s < STAGES - 1; ++s) {
            mbar_expect_tx(mb0 + 8u * s, STG_BYTES);
            bulk_g2s(sg0 + (unsigned)(s * STG_BYTES), xrow + (size_t)s * STG_BYTES,
                     STG_BYTES, mb0 + 8u * s);
        }
    }

    // ---- prologue (overlaps with in-flight bulk copies) ----
    const float2 s0 = __ldg((const float2*)xrow);          // (q0, pi0)
    const float y0 = __ldg(&y_pred[bidx * 3 + 0]);
    const float y1 = __ldg(&y_pred[bidx * 3 + 1]);
    const float y2 = __ldg(&y_pred[bidx * 3 + 2]);
    const float m   = y0 + 0.1f;
    const float dtm = DT / m;
    const float dtk = DT * y1;
    const float dtl = DT * y2;

    // fp32 step operator: q' = q + dtm*pi ; pi' = -dtk*q' + (1-dtl)*pi
    M2f A;
    A.a = 1.0f;   A.b = dtm;
    A.c = -dtk;   A.d = 1.0f - dtl - dtk * dtm;

    // P = (A^2)^lane via binexp; chain ends with cur = A^64.
    M2f cur = m2mul(A, A);                        // A^2
    M2f P; P.a = 1.0f; P.b = 0.0f; P.c = 0.0f; P.d = 1.0f;
    unsigned e = (unsigned)lane;
    #pragma unroll
    for (int i = 0; i < 5; ++i) {
        if (e & 1u) P = m2mul(P, cur);
        e >>= 1;
        cur = m2mul(cur, cur);                    // ends at A^64
    }
    const M2f M64 = cur;

    // Seed this lane's state at t = 2*lane
    float q  = fmaf(P.a, s0.x, P.b * s0.y);
    float pi = fmaf(P.c, s0.x, P.d * s0.y);

    float w0 = (float)(T_SZ - 2 * lane);
    float accq = 0.0f, accp = 0.0f;

    // ---- main loop: smem ring, 3 bulk copies always in flight ----
    #pragma unroll
    for (int g = 0; g < NSTG; ++g) {
        const int slot = g & (STAGES - 1);
        mbar_wait(mb0 + 8u * slot, (unsigned)((g >> 2) & 1));

        // read the whole stage into registers (4 x LDS.128)
        float4 xv0 = stg[wid][slot][0][lane];
        float4 xv1 = stg[wid][slot][1][lane];
        float4 xv2 = stg[wid][slot][2][lane];
        float4 xv3 = stg[wid][slot][3][lane];

        // refill: stage g+3 into the slot consumed at group g-1
        if (g + STAGES - 1 < NSTG && lane == 0) {
            const int gn = g + STAGES - 1;
            const int sn = gn & (STAGES - 1);
            mbar_expect_tx(mb0 + 8u * sn, STG_BYTES);
            bulk_g2s(sg0 + (unsigned)(sn * STG_BYTES), xrow + (size_t)gn * STG_BYTES,
                     STG_BYTES, mb0 + 8u * sn);
        }

        const float4 xvs[4] = {xv0, xv1, xv2, xv3};
        #pragma unroll
        for (int j = 0; j < WIN_PER_STG; ++j) {
            const float4 xv = xvs[j];

            const float dq0 = q  - xv.x;
            const float dp0 = pi - xv.y;
            accq = fmaf(w0 * dq0, dq0, accq);
            accp = fmaf(w0 * dp0, dp0, accp);

            // exact fp32 step for t+1
            const float q1  = fmaf(dtm, pi, q);
            const float pi1 = fmaf(-dtk, q1, fmaf(-dtl, pi, pi));
            const float dq1 = q1  - xv.z;
            const float dp1 = pi1 - xv.w;
            const float w1 = w0 - 1.0f;
            accq = fmaf(w1 * dq1, dq1, accq);
            accp = fmaf(w1 * dp1, dp1, accp);

            // advance window state by A^64
            const float qn  = fmaf(M64.a, q, M64.b * pi);
            const float pin = fmaf(M64.c, q, M64.d * pi);
            q = qn; pi = pin;
            w0 -= 64.0f;
        }
    }

    // warp reduction
    #pragma unroll
    for (int off = 16; off; off >>= 1) {
        accq += __shfl_down_sync(0xffffffffu, accq, off);
        accp += __shfl_down_sync(0xffffffffu, accp, off);
    }

    if (lane == 0) {
        float pen = 0.0f;
        if (y0 < 0.0f) pen += expf(-10.0f * y0);
        if (y1 < 0.0f) pen += expf(-10.0f * y1);
        if (y2 < 0.0f) pen += expf(-10.0f * y2);
        s_q[wid] = accq; s_p[wid] = accp; s_n[wid] = pen;
    }
    __syncthreads();

    if (threadIdx.x == 0) {
        float bq = 0.0f, bp = 0.0f, bn = 0.0f;
        #pragma unroll
        for (int i = 0; i < WARPS_PER_BLOCK; ++i) { bq += s_q[i]; bp += s_p[i]; bn += s_n[i]; }
        g_blk[blockIdx.x] = make_float4(bq, bp, bn, 0.0f);
        __threadfence();
        unsigned c = atomicAdd(&g_cnt, 1u);
        isLast = (c == NBLOCKS - 1);
    }
    __syncthreads();

    // Last block: deterministic fixed-order final reduction over 1024 partials
    if (isLast) {
        const int t = threadIdx.x;          // 0..127
        double aq = 0.0, ap = 0.0, an = 0.0;
        #pragma unroll
        for (int i = 0; i < NBLOCKS / 128; ++i) {     // 8 independent loads
            const float4 v = __ldcg(&g_blk[t + 128 * i]);
            aq += (double)v.x; ap += (double)v.y; an += (double)v.z;
        }
        fsq[t] = aq; fsp[t] = ap; fsn[t] = an;
        __syncthreads();
        #pragma unroll
        for (int off = 64; off; off >>= 1) {
            if (t < off) { fsq[t] += fsq[t + off]; fsp[t] += fsp[t + off]; fsn[t] += fsn[t + off]; }
            __syncthreads();
        }
        if (t == 0) {
            double rq = sqrt(fsq[0] / (double)B_SZ);
            double rp = sqrt(fsp[0] / (double)B_SZ);
            rq = fmin(rq, 1.0e15);
            rp = fmin(rp, 1.0e15);
            double pen = fsn[0] / (double)(B_SZ * 3);
            pen = fmin(fmax(pen, 0.0), 1000.0);
            out[0] = (float)(0.5 * (rq + rp) + pen);
            g_cnt = 0;                 // reset for next graph replay
        }
    }
}

extern "C" void kernel_launch(void* const* d_in, const int* in_sizes, int n_in,
                              void* d_out, int out_size)
{
    int xi = 0, yi = 1;
    if (n_in >= 2 && in_sizes[0] == B_SZ * 3) { xi = 1; yi = 0; }
    const float* x       = (const float*)d_in[xi];
    const float* y_pred  = (const float*)d_in[yi];
    float* out = (float*)d_out;

    rollout_kernel<<<NBLOCKS, WARPS_PER_BLOCK * 32>>>(x, y_pred, out);
}

// round 15
// speedup vs baseline: 1.1753x; 1.1753x over previous
#include <cuda_runtime.h>
#include <cstdint>
#include <math.h>

#define B_SZ 4096
#define T_SZ 2048
#define WARPS_PER_BLOCK 4
#define NBLOCKS (B_SZ / WARPS_PER_BLOCK)   // 1024
#define NUNIT 16                            // 16 units of 128 timesteps per warp
#define RING 4                              // rolling ring depth (256-bit loads)
#define DT 0.01f

// Per-block partials: (sum_wq2, sum_wp2, penalty_sum, unused)
__device__ float4 g_blk[NBLOCKS];
__device__ unsigned g_cnt = 0;

struct M2f { float a, b, c, d; };   // [[a,b],[c,d]]

__device__ __forceinline__ M2f m2mul(const M2f& X, const M2f& Y) {
    M2f r;
    r.a = fmaf(X.a, Y.a, X.b * Y.c);
    r.b = fmaf(X.a, Y.b, X.b * Y.d);
    r.c = fmaf(X.c, Y.a, X.d * Y.c);
    r.d = fmaf(X.c, Y.b, X.d * Y.d);
    return r;
}

// 256-bit global load (sm_100a): 8 floats = 4 timesteps (q,pi pairs).
__device__ __forceinline__ void ldg256(const float* p, float* v) {
    unsigned r0, r1, r2, r3, r4, r5, r6, r7;
    asm volatile("ld.global.nc.v8.b32 {%0,%1,%2,%3,%4,%5,%6,%7}, [%8];"
                 : "=r"(r0), "=r"(r1), "=r"(r2), "=r"(r3),
                   "=r"(r4), "=r"(r5), "=r"(r6), "=r"(r7)
                 : "l"(p));
    v[0] = __uint_as_float(r0); v[1] = __uint_as_float(r1);
    v[2] = __uint_as_float(r2); v[3] = __uint_as_float(r3);
    v[4] = __uint_as_float(r4); v[5] = __uint_as_float(r5);
    v[6] = __uint_as_float(r6); v[7] = __uint_as_float(r7);
}

__global__ void __launch_bounds__(WARPS_PER_BLOCK * 32)
rollout_kernel(const float* __restrict__ x, const float* __restrict__ y_pred,
               float* __restrict__ out)
{
    __shared__ float s_q[WARPS_PER_BLOCK], s_p[WARPS_PER_BLOCK], s_n[WARPS_PER_BLOCK];
    __shared__ double fsq[128], fsp[128], fsn[128];
    __shared__ bool isLast;

    const int wid  = threadIdx.x >> 5;
    const int lane = threadIdx.x & 31;
    const int bidx = blockIdx.x * WARPS_PER_BLOCK + wid;   // batch index

    const float* xr = x + (size_t)bidx * (T_SZ * 2);

    // ---- rolling ring: fill all 4 slots up front ----
    float ring[RING][8];
    #pragma unroll
    for (int j = 0; j < RING; ++j)
        ldg256(xr + (size_t)(j * 32 + lane) * 8, ring[j]);
    const float q0t = __ldg(&xr[0]);
    const float p0t = __ldg(&xr[1]);

    // ---- prologue (overlaps with in-flight loads) ----
    const float y0 = __ldg(&y_pred[bidx * 3 + 0]);
    const float y1 = __ldg(&y_pred[bidx * 3 + 1]);
    const float y2 = __ldg(&y_pred[bidx * 3 + 2]);
    const float m   = y0 + 0.1f;
    const float dtm = DT / m;
    const float dtk = DT * y1;
    const float dtl = DT * y2;

    // fp32 step operator: q' = q + dtm*pi ; pi' = -dtk*q' + (1-dtl)*pi
    M2f A;
    A.a = 1.0f;   A.b = dtm;
    A.c = -dtk;   A.d = 1.0f - dtl - dtk * dtm;

    // P = (A^4)^lane via binexp; squaring ladder ends at cur = A^128.
    M2f cur = m2mul(A, A);                        // A^2
    cur = m2mul(cur, cur);                        // A^4
    M2f P; P.a = 1.0f; P.b = 0.0f; P.c = 0.0f; P.d = 1.0f;
    unsigned e = (unsigned)lane;
    #pragma unroll
    for (int i = 0; i < 5; ++i) {
        if (e & 1u) P = m2mul(P, cur);
        e >>= 1;
        cur = m2mul(cur, cur);                    // ends at A^128
    }
    const M2f M128 = cur;

    // Seed this lane's state at t = 4*lane
    float q  = fmaf(P.a, q0t, P.b * p0t);
    float pi = fmaf(P.c, q0t, P.d * p0t);

    float w0 = (float)(T_SZ - 4 * lane);          // weight at t = 4*lane
    float accq = 0.0f, accp = 0.0f;

    // ---- main loop: rolling ring, one reload issued per unit consumed ----
    #pragma unroll
    for (int g = 0; g < NUNIT; ++g) {
        const int slot = g & (RING - 1);
        float xv[8];
        #pragma unroll
        for (int k = 0; k < 8; ++k) xv[k] = ring[slot][k];

        // immediately refill the freed slot with unit g+RING (steady MLP=4)
        if (g + RING < NUNIT)
            ldg256(xr + (size_t)((g + RING) * 32 + lane) * 8, ring[slot]);

        float qq = q, pp = pi;
        float w = w0;
        #pragma unroll
        for (int s = 0; s < 4; ++s) {
            const float dq = qq - xv[2 * s];
            const float dp = pp - xv[2 * s + 1];
            accq = fmaf(w * dq, dq, accq);
            accp = fmaf(w * dp, dp, accp);
            w -= 1.0f;
            if (s < 3) {
                qq = fmaf(dtm, pp, qq);                    // exact fp32 step
                pp = fmaf(-dtk, qq, fmaf(-dtl, pp, pp));
            }
        }

        // advance window state by A^128
        const float qn  = fmaf(M128.a, q, M128.b * pi);
        const float pin = fmaf(M128.c, q, M128.d * pi);
        q = qn; pi = pin;
        w0 -= 128.0f;
    }

    // warp reduction
    #pragma unroll
    for (int off = 16; off; off >>= 1) {
        accq += __shfl_down_sync(0xffffffffu, accq, off);
        accp += __shfl_down_sync(0xffffffffu, accp, off);
    }

    if (lane == 0) {
        float pen = 0.0f;
        if (y0 < 0.0f) pen += expf(-10.0f * y0);
        if (y1 < 0.0f) pen += expf(-10.0f * y1);
        if (y2 < 0.0f) pen += expf(-10.0f * y2);
        s_q[wid] = accq; s_p[wid] = accp; s_n[wid] = pen;
    }
    __syncthreads();

    if (threadIdx.x == 0) {
        float bq = 0.0f, bp = 0.0f, bn = 0.0f;
        #pragma unroll
        for (int i = 0; i < WARPS_PER_BLOCK; ++i) { bq += s_q[i]; bp += s_p[i]; bn += s_n[i]; }
        g_blk[blockIdx.x] = make_float4(bq, bp, bn, 0.0f);
        __threadfence();
        unsigned c = atomicAdd(&g_cnt, 1u);
        isLast = (c == NBLOCKS - 1);
    }
    __syncthreads();

    // Last block: deterministic fixed-order final reduction over 1024 partials
    if (isLast) {
        const int t = threadIdx.x;          // 0..127
        double aq = 0.0, ap = 0.0, an = 0.0;
        #pragma unroll
        for (int i = 0; i < NBLOCKS / 128; ++i) {     // 8 independent loads
            const float4 v = __ldcg(&g_blk[t + 128 * i]);
            aq += (double)v.x; ap += (double)v.y; an += (double)v.z;
        }
        fsq[t] = aq; fsp[t] = ap; fsn[t] = an;
        __syncthreads();
        #pragma unroll
        for (int off = 64; off; off >>= 1) {
            if (t < off) { fsq[t] += fsq[t + off]; fsp[t] += fsp[t + off]; fsn[t] += fsn[t + off]; }
            __syncthreads();
        }
        if (t == 0) {
            double rq = sqrt(fsq[0] / (double)B_SZ);
            double rp = sqrt(fsp[0] / (double)B_SZ);
            rq = fmin(rq, 1.0e15);
            rp = fmin(rp, 1.0e15);
            double pen = fsn[0] / (double)(B_SZ * 3);
            pen = fmin(fmax(pen, 0.0), 1000.0);
            out[0] = (float)(0.5 * (rq + rp) + pen);
            g_cnt = 0;                 // reset for next graph replay
        }
    }
}

extern "C" void kernel_launch(void* const* d_in, const int* in_sizes, int n_in,
                              void* d_out, int out_size)
{
    int xi = 0, yi = 1;
    if (n_in >= 2 && in_sizes[0] == B_SZ * 3) { xi = 1; yi = 0; }
    const float* x       = (const float*)d_in[xi];
    const float* y_pred  = (const float*)d_in[yi];
    float* out = (float*)d_out;

    rollout_kernel<<<NBLOCKS, WARPS_PER_BLOCK * 32>>>(x, y_pred, out);
}